// round 15
// baseline (speedup 1.0000x reference)
#include <cuda_runtime.h>
#include <cuda_fp16.h>
#include <cstdint>

#define BATCH 2
#define SEQ   2048
#define NHEAD 16
#define HDIM  64
#define EDIM  1024

// Scratch (static device globals: allocation-free per harness rules)
__device__ __align__(16) __half g_q[(size_t)BATCH * NHEAD * SEQ * HDIM];  // pre-scaled by 1/8
__device__ __align__(16) __half g_k[(size_t)BATCH * NHEAD * SEQ * HDIM];
__device__ __align__(16) __half g_v[(size_t)BATCH * NHEAD * SEQ * HDIM];  // TRANSPOSED [b,h,d,s]
__device__ __align__(16) __half g_att[(size_t)BATCH * SEQ * EDIM];
__device__ __align__(16) __half g_xc[(size_t)BATCH * SEQ * EDIM];
__device__ __align__(16) __half g_wqkv[(size_t)3 * EDIM * EDIM];
__device__ __align__(16) __half g_wfc[(size_t)EDIM * EDIM];

__device__ __forceinline__ float ex2f(float x) {
    float y;
    asm("ex2.approx.ftz.f32 %0, %1;" : "=f"(y) : "f"(x));
    return y;
}

// packed half2 exp2
__device__ __forceinline__ uint32_t h2ex2(uint32_t x) {
    uint32_t y;
    asm("ex2.approx.f16x2 %0, %1;" : "=r"(y) : "r"(x));
    return y;
}

__device__ __forceinline__ uint32_t smem_u32(const void* p) {
    return (uint32_t)__cvta_generic_to_shared(p);
}

__device__ __forceinline__ uint32_t pack_h2(float lo, float hi) {
    __half2 h = __floats2half2_rn(lo, hi);
    return *(uint32_t*)&h;
}

#define CP_A16(dst, src) \
    asm volatile("cp.async.cg.shared.global [%0], [%1], 16;" :: "r"(dst), "l"(src) : "memory")
#define CP_COMMIT() asm volatile("cp.async.commit_group;" ::: "memory")
#define CP_WAIT0()  asm volatile("cp.async.wait_group 0;" ::: "memory")
#define CP_WAIT1()  asm volatile("cp.async.wait_group 1;" ::: "memory")

// fp16 MMA, fp32 accumulate: D[16x8] += A[16x16] * B[16x8]
__device__ __forceinline__ void mma_f16(float* c, const uint32_t* a, const uint32_t* b) {
    asm volatile(
        "mma.sync.aligned.m16n8k16.row.col.f32.f16.f16.f32 "
        "{%0,%1,%2,%3}, {%4,%5,%6,%7}, {%8,%9}, {%0,%1,%2,%3};"
        : "+f"(c[0]), "+f"(c[1]), "+f"(c[2]), "+f"(c[3])
        : "r"(a[0]), "r"(a[1]), "r"(a[2]), "r"(a[3]), "r"(b[0]), "r"(b[1]));
}

__device__ __forceinline__ void ldsm_x4(uint32_t& r0, uint32_t& r1,
                                        uint32_t& r2, uint32_t& r3, uint32_t addr) {
    asm volatile("ldmatrix.sync.aligned.m8n8.x4.shared.b16 {%0,%1,%2,%3}, [%4];"
                 : "=r"(r0), "=r"(r1), "=r"(r2), "=r"(r3) : "r"(addr));
}

// ---------------------------------------------------------------------------
// Fused fp32 -> fp16 conversion of x, qkv_w, fc_w in ONE launch.
// ---------------------------------------------------------------------------
#define N4_X  (BATCH * SEQ * EDIM / 4)       // 1048576
#define N4_WQ (3 * EDIM * EDIM / 4)          //  786432
#define N4_WF (EDIM * EDIM / 4)              //  262144

__global__ __launch_bounds__(512)
void cvt_all_kernel(const float* __restrict__ x,
                    const float* __restrict__ wq,
                    const float* __restrict__ wf)
{
    int i = blockIdx.x * blockDim.x + threadIdx.x;
    const float* src;
    __half* dst;
    int j;
    if (i < N4_X)                { src = x;  dst = g_xc;   j = i; }
    else if (i < N4_X + N4_WQ)   { src = wq; dst = g_wqkv; j = i - N4_X; }
    else if (i < N4_X + N4_WQ + N4_WF) { src = wf; dst = g_wfc; j = i - N4_X - N4_WQ; }
    else return;
    float4 v = ((const float4*)src)[j];
    __half2* o = (__half2*)dst;
    o[2 * j]     = __floats2half2_rn(v.x, v.y);
    o[2 * j + 1] = __floats2half2_rn(v.z, v.w);
}

// ---------------------------------------------------------------------------
// fp16 GEMM: C[M,N] = A[M,K] @ W[N,K]^T, fp32 accumulate. PERSISTENT CTAs.
// BM=BN=128, BK=64; 256 thr (4x2 warps, 32x64 warp tile); 3-stage cp.async,
// 1 barrier per K-step. smem row = 64 halves + 8 pad = 144B (CF ldmatrix).
// ---------------------------------------------------------------------------
template <int MODE>
__global__ __launch_bounds__(256, 2)
void gemm_f16_kernel(const float* __restrict__ bias,
                     const float* __restrict__ mask,
                     float* __restrict__ out,
                     int M, int N, int K, int NT, int NBX)
{
    extern __shared__ __half smh[];
    const int TILEB = 128 * 144;           // one operand tile, bytes
    const uint32_t smu = smem_u32(smh);

    const int tid  = threadIdx.x;
    const int warp = tid >> 5;
    const int lane = tid & 31;
    const int g    = lane >> 2;
    const int t    = lane & 3;
    const int wm   = warp >> 1;
    const int wn   = warp & 1;

    const uint32_t offpat = (uint32_t)(((lane & 8) + (lane & 7)) * 144 + ((lane >> 4) << 4));

    const __half* Ap = (MODE == 0) ? (const __half*)g_att : (const __half*)g_xc;
    const __half* Wp = (MODE == 0) ? (const __half*)g_wfc : (const __half*)g_wqkv;

    for (int tile = blockIdx.x; tile < NT; tile += gridDim.x) {
        const int m0 = (tile / NBX) * 128;
        const int n0 = (tile % NBX) * 128;

        auto gissue = [&](int st, int k0) {
            #pragma unroll
            for (int i = 0; i < 4; i++) {
                int idx = tid + i * 256;
                int row = idx >> 3;
                int cp  = (idx & 7) << 3;
                uint32_t dst = (uint32_t)(st * 2 * TILEB + row * 144 + cp * 2);
                CP_A16(smu + dst,         Ap + (size_t)(m0 + row) * K + k0 + cp);
                CP_A16(smu + dst + TILEB, Wp + (size_t)(n0 + row) * K + k0 + cp);
            }
            CP_COMMIT();
        };

        float acc[2][8][4] = {};

        const int NK = K / 64;
        gissue(0, 0);
        gissue(1, 64);

        for (int ki = 0; ki < NK; ki++) {
            if (ki + 2 < NK) { CP_WAIT1(); }
            else             { CP_WAIT0(); }
            __syncthreads();
            if (ki + 2 < NK) gissue((ki + 2) % 3, (ki + 2) * 64);

            const uint32_t stA = smu + (uint32_t)((ki % 3) * 2 * TILEB + wm * 32 * 144) + offpat;
            const uint32_t stB = smu + (uint32_t)((ki % 3) * 2 * TILEB + TILEB + wn * 64 * 144) + offpat;

            #pragma unroll
            for (int kk = 0; kk < 4; kk++) {
                uint32_t a[2][4];
                uint32_t bb[8][2];
                ldsm_x4(a[0][0], a[0][1], a[0][2], a[0][3], stA + kk * 32);
                ldsm_x4(a[1][0], a[1][1], a[1][2], a[1][3], stA + 16 * 144 + kk * 32);
                #pragma unroll
                for (int nb = 0; nb < 4; nb++)
                    ldsm_x4(bb[2 * nb][0], bb[2 * nb + 1][0], bb[2 * nb][1], bb[2 * nb + 1][1],
                            stB + nb * 16 * 144 + kk * 32);
                #pragma unroll
                for (int mi = 0; mi < 2; mi++)
                    #pragma unroll
                    for (int ni = 0; ni < 8; ni++)
                        mma_f16(acc[mi][ni], a[mi], bb[ni]);
            }
        }

        #pragma unroll
        for (int ni = 0; ni < 8; ni++) {
            const int base8 = n0 + wn * 64 + ni * 8;
            const int cc    = base8 + 2 * t;
            if (MODE == 0) {
                float b0 = bias[cc], b1 = bias[cc + 1];
                #pragma unroll
                for (int mi = 0; mi < 2; mi++) {
                    int r0 = m0 + wm * 32 + mi * 16 + g;
                    out[(size_t)r0 * N + cc]           = acc[mi][ni][0] + b0;
                    out[(size_t)r0 * N + cc + 1]       = acc[mi][ni][1] + b1;
                    out[(size_t)(r0 + 8) * N + cc]     = acc[mi][ni][2] + b0;
                    out[(size_t)(r0 + 8) * N + cc + 1] = acc[mi][ni][3] + b1;
                }
            } else {
                const int h     = base8 / 192;
                const int rem   = base8 - h * 192;
                const int which = rem >> 6;
                const int j     = (rem & 63) + 2 * t;
                float scm = mask[h];
                if (which == 0) scm *= 0.125f;        // fold 1/sqrt(hd) into q (exact pow2)
                const float b0  = bias[cc] * scm;
                const float b1  = bias[cc + 1] * scm;
                #pragma unroll
                for (int mi = 0; mi < 2; mi++) {
                    #pragma unroll
                    for (int half_ = 0; half_ < 2; half_++) {
                        int r = m0 + wm * 32 + mi * 16 + g + half_ * 8;
                        float v0 = acc[mi][ni][2 * half_]     * scm + b0;
                        float v1 = acc[mi][ni][2 * half_ + 1] * scm + b1;
                        int bb_ = r >> 11;
                        int s   = r & (SEQ - 1);
                        size_t bh = (size_t)(bb_ * NHEAD + h);
                        if (which == 0) {
                            *(__half2*)(g_q + (bh * SEQ + s) * HDIM + j) =
                                __floats2half2_rn(v0, v1);
                        } else if (which == 1) {
                            *(__half2*)(g_k + (bh * SEQ + s) * HDIM + j) =
                                __floats2half2_rn(v0, v1);
                        } else {
                            g_v[(bh * HDIM + j)     * SEQ + s] = __float2half_rn(v0);
                            g_v[(bh * HDIM + j + 1) * SEQ + s] = __float2half_rn(v1);
                        }
                    }
                }
            }
        }
        __syncthreads();
    }
}

// ---------------------------------------------------------------------------
// Flash attention (fp16 mma.sync, fp32 softmax/acc). PERSISTENT CTAs.
// FA2 register-P; Q pre-scaled; rescale skip; f16x2 exp; tensor-core row sum.
// NEW: 3-stage KV pipeline with ONE __syncthreads per KV-iter (GEMM pattern):
// slot (ki+2)%3 == (ki-1)%3 is provably free after the top-of-iter barrier.
// smem: Q 18KB + 3 x (K 9KB + V 9KB) = 73.7KB; 2 CTAs/SM = 147KB < 227KB.
// ---------------------------------------------------------------------------
__global__ __launch_bounds__(256, 2)
void flash_attn_kernel(int NT)
{
    extern __shared__ __half smh[];
    const int QTB = 128 * 144;    // Q region bytes
    const int STB = 64 * 144;     // one K (or V) stage, bytes; stage s at QTB + s*2*STB
    const uint32_t smu = smem_u32(smh);

    const int tid  = threadIdx.x;
    const int warp = tid >> 5;
    const int lane = tid & 31;
    const int g    = lane >> 2;
    const int t    = lane & 3;

    const uint32_t offpat = (uint32_t)(((lane & 8) + (lane & 7)) * 144 + ((lane >> 4) << 4));
    const uint32_t qBase = smu + (uint32_t)(warp * 16 * 144) + offpat;
    const float LOG2E = 1.4426950408889634f;
    const uint32_t ONES2 = 0x3C003C00u;           // half2(1.0, 1.0)
    const uint32_t bb_ones[2] = {ONES2, ONES2};

    for (int tile = blockIdx.x; tile < NT; tile += gridDim.x) {
        const int qt = tile & (SEQ / 128 - 1);          // 0..15
        const int h  = (tile >> 4) & (NHEAD - 1);       // 0..15
        const int b  = tile >> 8;                        // 0..1

        const size_t baseQK = ((size_t)(b * NHEAD + h)) * SEQ * HDIM;
        const __half* Qg = g_q + baseQK + (size_t)qt * 128 * HDIM;
        const __half* Kg = g_k + baseQK;
        const __half* Vg = g_v + ((size_t)(b * NHEAD + h)) * HDIM * SEQ;   // [d][s]

        // Q load (own cp.async group)
        #pragma unroll
        for (int i = 0; i < 4; i++) {
            int idx = tid + i * 256;
            int row = idx >> 3;
            int cp  = (idx & 7) << 3;
            CP_A16(smu + (uint32_t)(row * 144 + cp * 2), Qg + row * HDIM + cp);
        }
        CP_COMMIT();

        auto load_kv = [&](int st, int kt) {
            uint32_t base = smu + (uint32_t)(QTB + st * 2 * STB);
            #pragma unroll
            for (int i = 0; i < 2; i++) {
                int idx = tid + i * 256;
                int row = idx >> 3;
                int cp  = (idx & 7) << 3;
                CP_A16(base + (uint32_t)(row * 144 + cp * 2),
                       Kg + ((size_t)kt * 64 + row) * HDIM + cp);
                CP_A16(base + (uint32_t)(STB + row * 144 + cp * 2),
                       Vg + (size_t)row * SEQ + kt * 64 + cp);
            }
            CP_COMMIT();
        };

        load_kv(0, 0);
        load_kv(1, 1);

        float oc[8][4] = {};
        float lc[4]    = {};                    // tensor-core row sums (ones column)
        float m0 = -1e30f, m1 = -1e30f;
        uint32_t qa[4][4];
        bool qloaded = false;

        const int NK = SEQ / 64;                // 32
        for (int ki = 0; ki < NK; ki++) {
            if (ki + 2 < NK) { CP_WAIT1(); }    // stage ki done (Q done too at ki=0)
            else             { CP_WAIT0(); }
            __syncthreads();
            if (ki + 2 < NK) load_kv((ki + 2) % 3, ki + 2);

            if (!qloaded) {                     // first iter: extract Q fragments
                #pragma unroll
                for (int kk = 0; kk < 4; kk++)
                    ldsm_x4(qa[kk][0], qa[kk][1], qa[kk][2], qa[kk][3], qBase + kk * 32);
                qloaded = true;
            }

            const uint32_t kBase = smu + (uint32_t)(QTB + (ki % 3) * 2 * STB) + offpat;
            const uint32_t vBase = kBase + (uint32_t)STB;

            // S = Q @ K^T  (already includes 1/sqrt(hd) via pre-scaled Q)
            float sc[8][4] = {};
            #pragma unroll
            for (int kk = 0; kk < 4; kk++) {
                uint32_t bb[8][2];
                #pragma unroll
                for (int nb = 0; nb < 4; nb++)
                    ldsm_x4(bb[2 * nb][0], bb[2 * nb + 1][0], bb[2 * nb][1], bb[2 * nb + 1][1],
                            kBase + nb * 16 * 144 + kk * 32);
                #pragma unroll
                for (int ni = 0; ni < 8; ni++)
                    mma_f16(sc[ni], qa[kk], bb[ni]);
            }

            // online softmax max update (rows g, g+8)
            float mx0 = -1e30f, mx1 = -1e30f;
            #pragma unroll
            for (int ni = 0; ni < 8; ni++) {
                mx0 = fmaxf(mx0, fmaxf(sc[ni][0], sc[ni][1]));
                mx1 = fmaxf(mx1, fmaxf(sc[ni][2], sc[ni][3]));
            }
            mx0 = fmaxf(mx0, __shfl_xor_sync(0xffffffffu, mx0, 1));
            mx0 = fmaxf(mx0, __shfl_xor_sync(0xffffffffu, mx0, 2));
            mx1 = fmaxf(mx1, __shfl_xor_sync(0xffffffffu, mx1, 1));
            mx1 = fmaxf(mx1, __shfl_xor_sync(0xffffffffu, mx1, 2));

            // warp-uniform rescale skip: if no lane's max grew, a0=a1=1 exactly.
            bool grew = (mx0 > m0) || (mx1 > m1);
            if (__any_sync(0xffffffffu, grew)) {
                float mn0 = fmaxf(m0, mx0);
                float mn1 = fmaxf(m1, mx1);
                float a0 = ex2f((m0 - mn0) * LOG2E);
                float a1 = ex2f((m1 - mn1) * LOG2E);
                m0 = mn0; m1 = mn1;
                lc[0] *= a0; lc[1] *= a0; lc[2] *= a1; lc[3] *= a1;
                #pragma unroll
                for (int ni = 0; ni < 8; ni++) {
                    oc[ni][0] *= a0; oc[ni][1] *= a0;
                    oc[ni][2] *= a1; oc[ni][3] *= a1;
                }
            }

            // P = exp2((s - m) * log2e) in half2 (one f16x2 MUFU per pair)
            const float mL0 = m0 * LOG2E;
            const float mL1 = m1 * LOG2E;
            uint32_t ph01[8], ph23[8];
            #pragma unroll
            for (int ni = 0; ni < 8; ni++) {
                ph01[ni] = h2ex2(pack_h2(fmaf(sc[ni][0], LOG2E, -mL0),
                                         fmaf(sc[ni][1], LOG2E, -mL0)));
                ph23[ni] = h2ex2(pack_h2(fmaf(sc[ni][2], LOG2E, -mL1),
                                         fmaf(sc[ni][3], LOG2E, -mL1)));
            }

            // O += P @ V ; l += P @ 1 (tensor-core row sum, same rescale path)
            #pragma unroll
            for (int kk = 0; kk < 4; kk++) {
                uint32_t pa[4];
                pa[0] = ph01[2 * kk];
                pa[1] = ph23[2 * kk];
                pa[2] = ph01[2 * kk + 1];
                pa[3] = ph23[2 * kk + 1];
                uint32_t bb[8][2];
                #pragma unroll
                for (int nb = 0; nb < 4; nb++)
                    ldsm_x4(bb[2 * nb][0], bb[2 * nb + 1][0], bb[2 * nb][1], bb[2 * nb + 1][1],
                            vBase + nb * 16 * 144 + kk * 32);
                #pragma unroll
                for (int ni = 0; ni < 8; ni++)
                    mma_f16(oc[ni], pa, bb[ni]);
                mma_f16(lc, pa, bb_ones);
            }
            // no bottom barrier: next iter's top barrier gates slot reuse
        }

        float i0 = 1.0f / lc[0];
        float i1 = 1.0f / lc[2];
        int r0 = qt * 128 + warp * 16 + g;
        __half* Og = g_att + (size_t)b * SEQ * EDIM + (size_t)h * HDIM;
        #pragma unroll
        for (int ni = 0; ni < 8; ni++) {
            int cc = ni * 8 + 2 * t;
            *(__half2*)(Og + (size_t)r0 * EDIM + cc) =
                __floats2half2_rn(oc[ni][0] * i0, oc[ni][1] * i0);
            *(__half2*)(Og + (size_t)(r0 + 8) * EDIM + cc) =
                __floats2half2_rn(oc[ni][2] * i1, oc[ni][3] * i1);
        }
        __syncthreads();   // MUST precede next tile's prologue cp.async issues
    }
}

extern "C" void kernel_launch(void* const* d_in, const int* in_sizes, int n_in,
                              void* d_out, int out_size)
{
    const float* x     = (const float*)d_in[0];
    const float* hmask = (const float*)d_in[1];
    const float* qkv_w = (const float*)d_in[2];
    const float* qkv_b = (const float*)d_in[3];
    const float* fc_w  = (const float*)d_in[4];
    const float* fc_b  = (const float*)d_in[5];
    float* out = (float*)d_out;

    const int gemm_smem = 3 * 2 * 128 * 144;                 // 110592 B
    const int fa_smem   = 128 * 144 + 3 * 2 * 64 * 144;      // 73728 B

    cudaFuncSetAttribute(gemm_f16_kernel<1>,
                         cudaFuncAttributeMaxDynamicSharedMemorySize, gemm_smem);
    cudaFuncSetAttribute(gemm_f16_kernel<0>,
                         cudaFuncAttributeMaxDynamicSharedMemorySize, gemm_smem);
    cudaFuncSetAttribute(flash_attn_kernel,
                         cudaFuncAttributeMaxDynamicSharedMemorySize, fa_smem);

    // 0) one fused fp32->fp16 conversion launch (x, qkv_w, fc_w)
    {
        int total4 = N4_X + N4_WQ + N4_WF;
        cvt_all_kernel<<<(total4 + 511) / 512, 512>>>(x, qkv_w, fc_w);
    }

    const int PERSIST = 296;   // 148 SMs x 2 CTAs

    // 1) QKV projection + bias + head_mask (+1/8 into q) + scatter (persistent)
    {
        int NT  = (BATCH * SEQ / 128) * (3 * EDIM / 128);   // 768
        int NBX = 3 * EDIM / 128;                           // 24
        gemm_f16_kernel<1><<<PERSIST, 256, gemm_smem>>>(
            qkv_b, hmask, nullptr, BATCH * SEQ, 3 * EDIM, EDIM, NT, NBX);
    }

    // 2) flash attention -> g_att [B,S,D] (fp16, persistent)
    {
        int NT = (SEQ / 128) * NHEAD * BATCH;               // 512
        flash_attn_kernel<<<PERSIST, 256, fa_smem>>>(NT);
    }

    // 3) output projection + bias -> d_out (fp32; 256 tiles = 1 wave)
    {
        int NT  = (BATCH * SEQ / 128) * (EDIM / 128);       // 256
        int NBX = EDIM / 128;                               // 8
        gemm_f16_kernel<0><<<NT, 256, gemm_smem>>>(
            fc_b, nullptr, out, BATCH * SEQ, EDIM, EDIM, NT, NBX);
    }
}

// round 16
// speedup vs baseline: 1.0142x; 1.0142x over previous
#include <cuda_runtime.h>
#include <cuda_fp16.h>
#include <cstdint>

#define BATCH 2
#define SEQ   2048
#define NHEAD 16
#define HDIM  64
#define EDIM  1024

// Scratch (static device globals: allocation-free per harness rules)
__device__ __align__(16) __half g_q[(size_t)BATCH * NHEAD * SEQ * HDIM];  // pre-scaled by 1/8
__device__ __align__(16) __half g_k[(size_t)BATCH * NHEAD * SEQ * HDIM];
__device__ __align__(16) __half g_v[(size_t)BATCH * NHEAD * SEQ * HDIM];  // TRANSPOSED [b,h,d,s]
__device__ __align__(16) __half g_att[(size_t)BATCH * SEQ * EDIM];
__device__ __align__(16) __half g_xc[(size_t)BATCH * SEQ * EDIM];
__device__ __align__(16) __half g_wqkv[(size_t)3 * EDIM * EDIM];
__device__ __align__(16) __half g_wfc[(size_t)EDIM * EDIM];

__device__ __forceinline__ float ex2f(float x) {
    float y;
    asm("ex2.approx.ftz.f32 %0, %1;" : "=f"(y) : "f"(x));
    return y;
}

// packed half2 exp2
__device__ __forceinline__ uint32_t h2ex2(uint32_t x) {
    uint32_t y;
    asm("ex2.approx.f16x2 %0, %1;" : "=r"(y) : "r"(x));
    return y;
}

__device__ __forceinline__ uint32_t smem_u32(const void* p) {
    return (uint32_t)__cvta_generic_to_shared(p);
}

__device__ __forceinline__ uint32_t pack_h2(float lo, float hi) {
    __half2 h = __floats2half2_rn(lo, hi);
    return *(uint32_t*)&h;
}

#define CP_A16(dst, src) \
    asm volatile("cp.async.cg.shared.global [%0], [%1], 16;" :: "r"(dst), "l"(src) : "memory")
#define CP_COMMIT() asm volatile("cp.async.commit_group;" ::: "memory")
#define CP_WAIT0()  asm volatile("cp.async.wait_group 0;" ::: "memory")
#define CP_WAIT1()  asm volatile("cp.async.wait_group 1;" ::: "memory")

// fp16 MMA, fp32 accumulate: D[16x8] += A[16x16] * B[16x8]
__device__ __forceinline__ void mma_f16(float* c, const uint32_t* a, const uint32_t* b) {
    asm volatile(
        "mma.sync.aligned.m16n8k16.row.col.f32.f16.f16.f32 "
        "{%0,%1,%2,%3}, {%4,%5,%6,%7}, {%8,%9}, {%0,%1,%2,%3};"
        : "+f"(c[0]), "+f"(c[1]), "+f"(c[2]), "+f"(c[3])
        : "r"(a[0]), "r"(a[1]), "r"(a[2]), "r"(a[3]), "r"(b[0]), "r"(b[1]));
}

__device__ __forceinline__ void ldsm_x4(uint32_t& r0, uint32_t& r1,
                                        uint32_t& r2, uint32_t& r3, uint32_t addr) {
    asm volatile("ldmatrix.sync.aligned.m8n8.x4.shared.b16 {%0,%1,%2,%3}, [%4];"
                 : "=r"(r0), "=r"(r1), "=r"(r2), "=r"(r3) : "r"(addr));
}

// ---------------------------------------------------------------------------
// Fused fp32 -> fp16 conversion of x and qkv_w (fc_w is converted inside the
// FA kernel, hidden under its compute-bound execution).
// ---------------------------------------------------------------------------
#define N4_X  (BATCH * SEQ * EDIM / 4)       // 1048576
#define N4_WQ (3 * EDIM * EDIM / 4)          //  786432
#define N4_WF (EDIM * EDIM / 4)              //  262144

__global__ __launch_bounds__(512)
void cvt_all_kernel(const float* __restrict__ x,
                    const float* __restrict__ wq)
{
    int i = blockIdx.x * blockDim.x + threadIdx.x;
    const float* src;
    __half* dst;
    int j;
    if (i < N4_X)                    { src = x;  dst = g_xc;   j = i; }
    else if (i < N4_X + N4_WQ)       { src = wq; dst = g_wqkv; j = i - N4_X; }
    else return;
    float4 v = ((const float4*)src)[j];
    __half2* o = (__half2*)dst;
    o[2 * j]     = __floats2half2_rn(v.x, v.y);
    o[2 * j + 1] = __floats2half2_rn(v.z, v.w);
}

// ---------------------------------------------------------------------------
// fp16 GEMM: C[M,N] = A[M,K] @ W[N,K]^T, fp32 accumulate. PERSISTENT CTAs.
// BM=BN=128, BK=64; 256 thr (4x2 warps, 32x64 warp tile); 3-stage cp.async,
// 1 barrier per K-step. smem row = 64 halves + 8 pad = 144B (CF ldmatrix).
// ---------------------------------------------------------------------------
template <int MODE>
__global__ __launch_bounds__(256, 2)
void gemm_f16_kernel(const float* __restrict__ bias,
                     const float* __restrict__ mask,
                     float* __restrict__ out,
                     int M, int N, int K, int NT, int NBX)
{
    extern __shared__ __half smh[];
    const int TILEB = 128 * 144;           // one operand tile, bytes
    const uint32_t smu = smem_u32(smh);

    const int tid  = threadIdx.x;
    const int warp = tid >> 5;
    const int lane = tid & 31;
    const int g    = lane >> 2;
    const int t    = lane & 3;
    const int wm   = warp >> 1;
    const int wn   = warp & 1;

    const uint32_t offpat = (uint32_t)(((lane & 8) + (lane & 7)) * 144 + ((lane >> 4) << 4));

    const __half* Ap = (MODE == 0) ? (const __half*)g_att : (const __half*)g_xc;
    const __half* Wp = (MODE == 0) ? (const __half*)g_wfc : (const __half*)g_wqkv;

    for (int tile = blockIdx.x; tile < NT; tile += gridDim.x) {
        const int m0 = (tile / NBX) * 128;
        const int n0 = (tile % NBX) * 128;

        auto gissue = [&](int st, int k0) {
            #pragma unroll
            for (int i = 0; i < 4; i++) {
                int idx = tid + i * 256;
                int row = idx >> 3;
                int cp  = (idx & 7) << 3;
                uint32_t dst = (uint32_t)(st * 2 * TILEB + row * 144 + cp * 2);
                CP_A16(smu + dst,         Ap + (size_t)(m0 + row) * K + k0 + cp);
                CP_A16(smu + dst + TILEB, Wp + (size_t)(n0 + row) * K + k0 + cp);
            }
            CP_COMMIT();
        };

        float acc[2][8][4] = {};

        const int NK = K / 64;
        gissue(0, 0);
        gissue(1, 64);

        for (int ki = 0; ki < NK; ki++) {
            if (ki + 2 < NK) { CP_WAIT1(); }
            else             { CP_WAIT0(); }
            __syncthreads();
            if (ki + 2 < NK) gissue((ki + 2) % 3, (ki + 2) * 64);

            const uint32_t stA = smu + (uint32_t)((ki % 3) * 2 * TILEB + wm * 32 * 144) + offpat;
            const uint32_t stB = smu + (uint32_t)((ki % 3) * 2 * TILEB + TILEB + wn * 64 * 144) + offpat;

            #pragma unroll
            for (int kk = 0; kk < 4; kk++) {
                uint32_t a[2][4];
                uint32_t bb[8][2];
                ldsm_x4(a[0][0], a[0][1], a[0][2], a[0][3], stA + kk * 32);
                ldsm_x4(a[1][0], a[1][1], a[1][2], a[1][3], stA + 16 * 144 + kk * 32);
                #pragma unroll
                for (int nb = 0; nb < 4; nb++)
                    ldsm_x4(bb[2 * nb][0], bb[2 * nb + 1][0], bb[2 * nb][1], bb[2 * nb + 1][1],
                            stB + nb * 16 * 144 + kk * 32);
                #pragma unroll
                for (int mi = 0; mi < 2; mi++)
                    #pragma unroll
                    for (int ni = 0; ni < 8; ni++)
                        mma_f16(acc[mi][ni], a[mi], bb[ni]);
            }
        }

        #pragma unroll
        for (int ni = 0; ni < 8; ni++) {
            const int base8 = n0 + wn * 64 + ni * 8;
            const int cc    = base8 + 2 * t;
            if (MODE == 0) {
                float b0 = bias[cc], b1 = bias[cc + 1];
                #pragma unroll
                for (int mi = 0; mi < 2; mi++) {
                    int r0 = m0 + wm * 32 + mi * 16 + g;
                    out[(size_t)r0 * N + cc]           = acc[mi][ni][0] + b0;
                    out[(size_t)r0 * N + cc + 1]       = acc[mi][ni][1] + b1;
                    out[(size_t)(r0 + 8) * N + cc]     = acc[mi][ni][2] + b0;
                    out[(size_t)(r0 + 8) * N + cc + 1] = acc[mi][ni][3] + b1;
                }
            } else {
                const int h     = base8 / 192;
                const int rem   = base8 - h * 192;
                const int which = rem >> 6;
                const int j     = (rem & 63) + 2 * t;
                float scm = mask[h];
                if (which == 0) scm *= 0.125f;        // fold 1/sqrt(hd) into q (exact pow2)
                const float b0  = bias[cc] * scm;
                const float b1  = bias[cc + 1] * scm;
                #pragma unroll
                for (int mi = 0; mi < 2; mi++) {
                    #pragma unroll
                    for (int half_ = 0; half_ < 2; half_++) {
                        int r = m0 + wm * 32 + mi * 16 + g + half_ * 8;
                        float v0 = acc[mi][ni][2 * half_]     * scm + b0;
                        float v1 = acc[mi][ni][2 * half_ + 1] * scm + b1;
                        int bb_ = r >> 11;
                        int s   = r & (SEQ - 1);
                        size_t bh = (size_t)(bb_ * NHEAD + h);
                        if (which == 0) {
                            *(__half2*)(g_q + (bh * SEQ + s) * HDIM + j) =
                                __floats2half2_rn(v0, v1);
                        } else if (which == 1) {
                            *(__half2*)(g_k + (bh * SEQ + s) * HDIM + j) =
                                __floats2half2_rn(v0, v1);
                        } else {
                            g_v[(bh * HDIM + j)     * SEQ + s] = __float2half_rn(v0);
                            g_v[(bh * HDIM + j + 1) * SEQ + s] = __float2half_rn(v1);
                        }
                    }
                }
            }
        }
        __syncthreads();
    }
}

// ---------------------------------------------------------------------------
// Flash attention (fp16 mma.sync, fp32 softmax/acc). PERSISTENT CTAs.
// R14 structure: double-buffered 64-wide KV, 1 barrier + FA2 register-P,
// Q pre-scaled, rescale skip, f16x2 exp, tensor-core row sum.
// PLUS: converts fc_w -> g_wfc in its prologue (hidden; FA is compute-bound,
// DRAM ~3% busy). FC launches after FA => ordering by kernel serialization.
// ---------------------------------------------------------------------------
__global__ __launch_bounds__(256, 2)
void flash_attn_kernel(int NT, const float* __restrict__ wf)
{
    extern __shared__ __half smh[];
    const int QTB = 128 * 144;    // Q region bytes
    const int STB = 64 * 144;     // one K or V stage, bytes
    const uint32_t smu = smem_u32(smh);

    const int tid  = threadIdx.x;
    const int warp = tid >> 5;
    const int lane = tid & 31;
    const int g    = lane >> 2;
    const int t    = lane & 3;

    // side job: convert fc_w (fp32 -> fp16), grid-stride; ~3.5 float4/thread
    {
        int nthr = gridDim.x * 256;
        for (int i = blockIdx.x * 256 + tid; i < N4_WF; i += nthr) {
            float4 v = ((const float4*)wf)[i];
            __half2* o = (__half2*)g_wfc;
            o[2 * i]     = __floats2half2_rn(v.x, v.y);
            o[2 * i + 1] = __floats2half2_rn(v.z, v.w);
        }
    }

    const uint32_t offpat = (uint32_t)(((lane & 8) + (lane & 7)) * 144 + ((lane >> 4) << 4));
    const uint32_t qBase = smu + (uint32_t)(warp * 16 * 144) + offpat;
    const float LOG2E = 1.4426950408889634f;
    const uint32_t ONES2 = 0x3C003C00u;           // half2(1.0, 1.0)
    const uint32_t bb_ones[2] = {ONES2, ONES2};

    for (int tile = blockIdx.x; tile < NT; tile += gridDim.x) {
        const int qt = tile & (SEQ / 128 - 1);          // 0..15
        const int h  = (tile >> 4) & (NHEAD - 1);       // 0..15
        const int b  = tile >> 8;                        // 0..1

        const size_t baseQK = ((size_t)(b * NHEAD + h)) * SEQ * HDIM;
        const __half* Qg = g_q + baseQK + (size_t)qt * 128 * HDIM;
        const __half* Kg = g_k + baseQK;
        const __half* Vg = g_v + ((size_t)(b * NHEAD + h)) * HDIM * SEQ;   // [d][s]

        #pragma unroll
        for (int i = 0; i < 4; i++) {
            int idx = tid + i * 256;
            int row = idx >> 3;
            int cp  = (idx & 7) << 3;
            CP_A16(smu + (uint32_t)(row * 144 + cp * 2), Qg + row * HDIM + cp);
        }
        CP_COMMIT();

        auto load_kv = [&](int st, int kt) {
            #pragma unroll
            for (int i = 0; i < 2; i++) {
                int idx = tid + i * 256;
                int row = idx >> 3;
                int cp  = (idx & 7) << 3;
                CP_A16(smu + (uint32_t)(QTB + st * STB + row * 144 + cp * 2),
                       Kg + ((size_t)kt * 64 + row) * HDIM + cp);
                CP_A16(smu + (uint32_t)(QTB + 2 * STB + st * STB + row * 144 + cp * 2),
                       Vg + (size_t)row * SEQ + kt * 64 + cp);
            }
            CP_COMMIT();
        };

        load_kv(0, 0);
        CP_WAIT1();       // Q group done (KV0 may still be in flight)
        __syncthreads();

        uint32_t qa[4][4];
        #pragma unroll
        for (int kk = 0; kk < 4; kk++)
            ldsm_x4(qa[kk][0], qa[kk][1], qa[kk][2], qa[kk][3], qBase + kk * 32);
        __syncthreads();

        float oc[8][4] = {};
        float lc[4]    = {};                    // tensor-core row sums (ones column)
        float m0 = -1e30f, m1 = -1e30f;

        int st = 0;
        for (int kt = 0; kt < SEQ / 64; kt++, st ^= 1) {
            if (kt + 1 < SEQ / 64) { load_kv(st ^ 1, kt + 1); CP_WAIT1(); }
            else                   { CP_WAIT0(); }
            __syncthreads();

            const uint32_t kBase = smu + (uint32_t)(QTB + st * STB) + offpat;
            const uint32_t vBase = smu + (uint32_t)(QTB + 2 * STB + st * STB) + offpat;

            // S = Q @ K^T  (already includes 1/sqrt(hd) via pre-scaled Q)
            float sc[8][4] = {};
            #pragma unroll
            for (int kk = 0; kk < 4; kk++) {
                uint32_t bb[8][2];
                #pragma unroll
                for (int nb = 0; nb < 4; nb++)
                    ldsm_x4(bb[2 * nb][0], bb[2 * nb + 1][0], bb[2 * nb][1], bb[2 * nb + 1][1],
                            kBase + nb * 16 * 144 + kk * 32);
                #pragma unroll
                for (int ni = 0; ni < 8; ni++)
                    mma_f16(sc[ni], qa[kk], bb[ni]);
            }

            // online softmax max update (rows g, g+8)
            float mx0 = -1e30f, mx1 = -1e30f;
            #pragma unroll
            for (int ni = 0; ni < 8; ni++) {
                mx0 = fmaxf(mx0, fmaxf(sc[ni][0], sc[ni][1]));
                mx1 = fmaxf(mx1, fmaxf(sc[ni][2], sc[ni][3]));
            }
            mx0 = fmaxf(mx0, __shfl_xor_sync(0xffffffffu, mx0, 1));
            mx0 = fmaxf(mx0, __shfl_xor_sync(0xffffffffu, mx0, 2));
            mx1 = fmaxf(mx1, __shfl_xor_sync(0xffffffffu, mx1, 1));
            mx1 = fmaxf(mx1, __shfl_xor_sync(0xffffffffu, mx1, 2));

            // warp-uniform rescale skip: if no lane's max grew, a0=a1=1 exactly.
            bool grew = (mx0 > m0) || (mx1 > m1);
            if (__any_sync(0xffffffffu, grew)) {
                float mn0 = fmaxf(m0, mx0);
                float mn1 = fmaxf(m1, mx1);
                float a0 = ex2f((m0 - mn0) * LOG2E);
                float a1 = ex2f((m1 - mn1) * LOG2E);
                m0 = mn0; m1 = mn1;
                lc[0] *= a0; lc[1] *= a0; lc[2] *= a1; lc[3] *= a1;
                #pragma unroll
                for (int ni = 0; ni < 8; ni++) {
                    oc[ni][0] *= a0; oc[ni][1] *= a0;
                    oc[ni][2] *= a1; oc[ni][3] *= a1;
                }
            }

            // P = exp2((s - m) * log2e) in half2 (one f16x2 MUFU per pair)
            const float mL0 = m0 * LOG2E;
            const float mL1 = m1 * LOG2E;
            uint32_t ph01[8], ph23[8];
            #pragma unroll
            for (int ni = 0; ni < 8; ni++) {
                ph01[ni] = h2ex2(pack_h2(fmaf(sc[ni][0], LOG2E, -mL0),
                                         fmaf(sc[ni][1], LOG2E, -mL0)));
                ph23[ni] = h2ex2(pack_h2(fmaf(sc[ni][2], LOG2E, -mL1),
                                         fmaf(sc[ni][3], LOG2E, -mL1)));
            }

            // O += P @ V ; l += P @ 1 (tensor-core row sum, same rescale path)
            #pragma unroll
            for (int kk = 0; kk < 4; kk++) {
                uint32_t pa[4];
                pa[0] = ph01[2 * kk];
                pa[1] = ph23[2 * kk];
                pa[2] = ph01[2 * kk + 1];
                pa[3] = ph23[2 * kk + 1];
                uint32_t bb[8][2];
                #pragma unroll
                for (int nb = 0; nb < 4; nb++)
                    ldsm_x4(bb[2 * nb][0], bb[2 * nb + 1][0], bb[2 * nb][1], bb[2 * nb + 1][1],
                            vBase + nb * 16 * 144 + kk * 32);
                #pragma unroll
                for (int ni = 0; ni < 8; ni++)
                    mma_f16(oc[ni], pa, bb[ni]);
                mma_f16(lc, pa, bb_ones);
            }
            __syncthreads();   // all warps done reading this KV stage
        }

        float i0 = 1.0f / lc[0];
        float i1 = 1.0f / lc[2];
        int r0 = qt * 128 + warp * 16 + g;
        __half* Og = g_att + (size_t)b * SEQ * EDIM + (size_t)h * HDIM;
        #pragma unroll
        for (int ni = 0; ni < 8; ni++) {
            int cc = ni * 8 + 2 * t;
            *(__half2*)(Og + (size_t)r0 * EDIM + cc) =
                __floats2half2_rn(oc[ni][0] * i0, oc[ni][1] * i0);
            *(__half2*)(Og + (size_t)(r0 + 8) * EDIM + cc) =
                __floats2half2_rn(oc[ni][2] * i1, oc[ni][3] * i1);
        }
        __syncthreads();
    }
}

extern "C" void kernel_launch(void* const* d_in, const int* in_sizes, int n_in,
                              void* d_out, int out_size)
{
    const float* x     = (const float*)d_in[0];
    const float* hmask = (const float*)d_in[1];
    const float* qkv_w = (const float*)d_in[2];
    const float* qkv_b = (const float*)d_in[3];
    const float* fc_w  = (const float*)d_in[4];
    const float* fc_b  = (const float*)d_in[5];
    float* out = (float*)d_out;

    const int gemm_smem = 3 * 2 * 128 * 144;                 // 110592 B
    const int fa_smem   = 128 * 144 + 4 * 64 * 144;          // 55296 B

    cudaFuncSetAttribute(gemm_f16_kernel<1>,
                         cudaFuncAttributeMaxDynamicSharedMemorySize, gemm_smem);
    cudaFuncSetAttribute(gemm_f16_kernel<0>,
                         cudaFuncAttributeMaxDynamicSharedMemorySize, gemm_smem);
    cudaFuncSetAttribute(flash_attn_kernel,
                         cudaFuncAttributeMaxDynamicSharedMemorySize, fa_smem);

    // 0) fp32->fp16 conversion of x + qkv_w (fc_w handled inside FA)
    {
        int total4 = N4_X + N4_WQ;
        cvt_all_kernel<<<(total4 + 511) / 512, 512>>>(x, qkv_w);
    }

    const int PERSIST = 296;   // 148 SMs x 2 CTAs

    // 1) QKV projection + bias + head_mask (+1/8 into q) + scatter (persistent)
    {
        int NT  = (BATCH * SEQ / 128) * (3 * EDIM / 128);   // 768
        int NBX = 3 * EDIM / 128;                           // 24
        gemm_f16_kernel<1><<<PERSIST, 256, gemm_smem>>>(
            qkv_b, hmask, nullptr, BATCH * SEQ, 3 * EDIM, EDIM, NT, NBX);
    }

    // 2) flash attention -> g_att [B,S,D] (fp16, persistent) + fc_w convert
    {
        int NT = (SEQ / 128) * NHEAD * BATCH;               // 512
        flash_attn_kernel<<<PERSIST, 256, fa_smem>>>(NT, fc_w);
    }

    // 3) output projection + bias -> d_out (fp32; 256 tiles = 1 wave)
    {
        int NT  = (BATCH * SEQ / 128) * (EDIM / 128);       // 256
        int NBX = EDIM / 128;                               // 8
        gemm_f16_kernel<0><<<NT, 256, gemm_smem>>>(
            fc_b, nullptr, out, BATCH * SEQ, EDIM, EDIM, NT, NBX);
    }
}

// round 17
// speedup vs baseline: 1.0403x; 1.0258x over previous
#include <cuda_runtime.h>
#include <cuda_fp16.h>
#include <cstdint>

#define BATCH 2
#define SEQ   2048
#define NHEAD 16
#define HDIM  64
#define EDIM  1024

// Scratch (static device globals: allocation-free per harness rules)
__device__ __align__(16) __half g_q[(size_t)BATCH * NHEAD * SEQ * HDIM];  // pre-scaled by 1/8
__device__ __align__(16) __half g_k[(size_t)BATCH * NHEAD * SEQ * HDIM];
__device__ __align__(16) __half g_v[(size_t)BATCH * NHEAD * SEQ * HDIM];  // TRANSPOSED [b,h,d,s]
__device__ __align__(16) __half g_att[(size_t)BATCH * SEQ * EDIM];
__device__ __align__(16) __half g_xc[(size_t)BATCH * SEQ * EDIM];
__device__ __align__(16) __half g_wqkv[(size_t)3 * EDIM * EDIM];
__device__ __align__(16) __half g_wfc[(size_t)EDIM * EDIM];
__device__ int g_ctr[4];                     // dynamic tile counters (reset in cvt)

__device__ __forceinline__ float ex2f(float x) {
    float y;
    asm("ex2.approx.ftz.f32 %0, %1;" : "=f"(y) : "f"(x));
    return y;
}

// packed half2 exp2
__device__ __forceinline__ uint32_t h2ex2(uint32_t x) {
    uint32_t y;
    asm("ex2.approx.f16x2 %0, %1;" : "=r"(y) : "r"(x));
    return y;
}

__device__ __forceinline__ uint32_t smem_u32(const void* p) {
    return (uint32_t)__cvta_generic_to_shared(p);
}

__device__ __forceinline__ uint32_t pack_h2(float lo, float hi) {
    __half2 h = __floats2half2_rn(lo, hi);
    return *(uint32_t*)&h;
}

#define CP_A16(dst, src) \
    asm volatile("cp.async.cg.shared.global [%0], [%1], 16;" :: "r"(dst), "l"(src) : "memory")
#define CP_COMMIT() asm volatile("cp.async.commit_group;" ::: "memory")
#define CP_WAIT0()  asm volatile("cp.async.wait_group 0;" ::: "memory")
#define CP_WAIT1()  asm volatile("cp.async.wait_group 1;" ::: "memory")

// fp16 MMA, fp32 accumulate: D[16x8] += A[16x16] * B[16x8]
__device__ __forceinline__ void mma_f16(float* c, const uint32_t* a, const uint32_t* b) {
    asm volatile(
        "mma.sync.aligned.m16n8k16.row.col.f32.f16.f16.f32 "
        "{%0,%1,%2,%3}, {%4,%5,%6,%7}, {%8,%9}, {%0,%1,%2,%3};"
        : "+f"(c[0]), "+f"(c[1]), "+f"(c[2]), "+f"(c[3])
        : "r"(a[0]), "r"(a[1]), "r"(a[2]), "r"(a[3]), "r"(b[0]), "r"(b[1]));
}

__device__ __forceinline__ void ldsm_x4(uint32_t& r0, uint32_t& r1,
                                        uint32_t& r2, uint32_t& r3, uint32_t addr) {
    asm volatile("ldmatrix.sync.aligned.m8n8.x4.shared.b16 {%0,%1,%2,%3}, [%4];"
                 : "=r"(r0), "=r"(r1), "=r"(r2), "=r"(r3) : "r"(addr));
}

// ---------------------------------------------------------------------------
// Fused fp32 -> fp16 conversion of x and qkv_w + counter reset.
// (fc_w is converted inside the FA kernel, hidden under its compute.)
// ---------------------------------------------------------------------------
#define N4_X  (BATCH * SEQ * EDIM / 4)       // 1048576
#define N4_WQ (3 * EDIM * EDIM / 4)          //  786432
#define N4_WF (EDIM * EDIM / 4)              //  262144

__global__ __launch_bounds__(512)
void cvt_all_kernel(const float* __restrict__ x,
                    const float* __restrict__ wq)
{
    int i = blockIdx.x * blockDim.x + threadIdx.x;
    if (i == 0) { g_ctr[0] = 0; g_ctr[1] = 0; g_ctr[2] = 0; }  // reset schedulers
    const float* src;
    __half* dst;
    int j;
    if (i < N4_X)                    { src = x;  dst = g_xc;   j = i; }
    else if (i < N4_X + N4_WQ)       { src = wq; dst = g_wqkv; j = i - N4_X; }
    else return;
    float4 v = ((const float4*)src)[j];
    __half2* o = (__half2*)dst;
    o[2 * j]     = __floats2half2_rn(v.x, v.y);
    o[2 * j + 1] = __floats2half2_rn(v.z, v.w);
}

// ---------------------------------------------------------------------------
// fp16 GEMM: C[M,N] = A[M,K] @ W[N,K]^T, fp32 accumulate.
// DYNAMIC tile stealing via g_ctr[MODE]. BM=BN=128, BK=64; 256 thr;
// 3-stage cp.async, 1 barrier per K-step; smem row 144B (CF ldmatrix).
// ---------------------------------------------------------------------------
template <int MODE>
__global__ __launch_bounds__(256, 2)
void gemm_f16_kernel(const float* __restrict__ bias,
                     const float* __restrict__ mask,
                     float* __restrict__ out,
                     int M, int N, int K, int NT, int NBX)
{
    extern __shared__ __half smh[];
    __shared__ int s_tile;
    const int TILEB = 128 * 144;           // one operand tile, bytes
    const uint32_t smu = smem_u32(smh);

    const int tid  = threadIdx.x;
    const int warp = tid >> 5;
    const int lane = tid & 31;
    const int g    = lane >> 2;
    const int t    = lane & 3;
    const int wm   = warp >> 1;
    const int wn   = warp & 1;

    const uint32_t offpat = (uint32_t)(((lane & 8) + (lane & 7)) * 144 + ((lane >> 4) << 4));

    const __half* Ap = (MODE == 0) ? (const __half*)g_att : (const __half*)g_xc;
    const __half* Wp = (MODE == 0) ? (const __half*)g_wfc : (const __half*)g_wqkv;

    for (;;) {
        if (tid == 0) s_tile = atomicAdd(&g_ctr[MODE], 1);
        __syncthreads();
        const int tile = s_tile;
        if (tile >= NT) break;
        const int m0 = (tile / NBX) * 128;
        const int n0 = (tile % NBX) * 128;

        auto gissue = [&](int st, int k0) {
            #pragma unroll
            for (int i = 0; i < 4; i++) {
                int idx = tid + i * 256;
                int row = idx >> 3;
                int cp  = (idx & 7) << 3;
                uint32_t dst = (uint32_t)(st * 2 * TILEB + row * 144 + cp * 2);
                CP_A16(smu + dst,         Ap + (size_t)(m0 + row) * K + k0 + cp);
                CP_A16(smu + dst + TILEB, Wp + (size_t)(n0 + row) * K + k0 + cp);
            }
            CP_COMMIT();
        };

        float acc[2][8][4] = {};

        const int NK = K / 64;
        gissue(0, 0);
        gissue(1, 64);

        for (int ki = 0; ki < NK; ki++) {
            if (ki + 2 < NK) { CP_WAIT1(); }
            else             { CP_WAIT0(); }
            __syncthreads();
            if (ki + 2 < NK) gissue((ki + 2) % 3, (ki + 2) * 64);

            const uint32_t stA = smu + (uint32_t)((ki % 3) * 2 * TILEB + wm * 32 * 144) + offpat;
            const uint32_t stB = smu + (uint32_t)((ki % 3) * 2 * TILEB + TILEB + wn * 64 * 144) + offpat;

            #pragma unroll
            for (int kk = 0; kk < 4; kk++) {
                uint32_t a[2][4];
                uint32_t bb[8][2];
                ldsm_x4(a[0][0], a[0][1], a[0][2], a[0][3], stA + kk * 32);
                ldsm_x4(a[1][0], a[1][1], a[1][2], a[1][3], stA + 16 * 144 + kk * 32);
                #pragma unroll
                for (int nb = 0; nb < 4; nb++)
                    ldsm_x4(bb[2 * nb][0], bb[2 * nb + 1][0], bb[2 * nb][1], bb[2 * nb + 1][1],
                            stB + nb * 16 * 144 + kk * 32);
                #pragma unroll
                for (int mi = 0; mi < 2; mi++)
                    #pragma unroll
                    for (int ni = 0; ni < 8; ni++)
                        mma_f16(acc[mi][ni], a[mi], bb[ni]);
            }
        }

        #pragma unroll
        for (int ni = 0; ni < 8; ni++) {
            const int base8 = n0 + wn * 64 + ni * 8;
            const int cc    = base8 + 2 * t;
            if (MODE == 0) {
                float b0 = bias[cc], b1 = bias[cc + 1];
                #pragma unroll
                for (int mi = 0; mi < 2; mi++) {
                    int r0 = m0 + wm * 32 + mi * 16 + g;
                    out[(size_t)r0 * N + cc]           = acc[mi][ni][0] + b0;
                    out[(size_t)r0 * N + cc + 1]       = acc[mi][ni][1] + b1;
                    out[(size_t)(r0 + 8) * N + cc]     = acc[mi][ni][2] + b0;
                    out[(size_t)(r0 + 8) * N + cc + 1] = acc[mi][ni][3] + b1;
                }
            } else {
                const int h     = base8 / 192;
                const int rem   = base8 - h * 192;
                const int which = rem >> 6;
                const int j     = (rem & 63) + 2 * t;
                float scm = mask[h];
                if (which == 0) scm *= 0.125f;        // fold 1/sqrt(hd) into q (exact pow2)
                const float b0  = bias[cc] * scm;
                const float b1  = bias[cc + 1] * scm;
                #pragma unroll
                for (int mi = 0; mi < 2; mi++) {
                    #pragma unroll
                    for (int half_ = 0; half_ < 2; half_++) {
                        int r = m0 + wm * 32 + mi * 16 + g + half_ * 8;
                        float v0 = acc[mi][ni][2 * half_]     * scm + b0;
                        float v1 = acc[mi][ni][2 * half_ + 1] * scm + b1;
                        int bb_ = r >> 11;
                        int s   = r & (SEQ - 1);
                        size_t bh = (size_t)(bb_ * NHEAD + h);
                        if (which == 0) {
                            *(__half2*)(g_q + (bh * SEQ + s) * HDIM + j) =
                                __floats2half2_rn(v0, v1);
                        } else if (which == 1) {
                            *(__half2*)(g_k + (bh * SEQ + s) * HDIM + j) =
                                __floats2half2_rn(v0, v1);
                        } else {
                            g_v[(bh * HDIM + j)     * SEQ + s] = __float2half_rn(v0);
                            g_v[(bh * HDIM + j + 1) * SEQ + s] = __float2half_rn(v1);
                        }
                    }
                }
            }
        }
        __syncthreads();   // protects smem stages AND s_tile for next grab
    }
}

// ---------------------------------------------------------------------------
// Flash attention (fp16 mma.sync, fp32 softmax/acc). DYNAMIC tile stealing.
// Double-buffered 64-wide KV, FA2 register-P, Q pre-scaled, rescale skip,
// f16x2 exp, tensor-core row sum. Converts fc_w in prologue (hidden).
// ---------------------------------------------------------------------------
__global__ __launch_bounds__(256, 2)
void flash_attn_kernel(int NT, const float* __restrict__ wf)
{
    extern __shared__ __half smh[];
    __shared__ int s_tile;
    const int QTB = 128 * 144;    // Q region bytes
    const int STB = 64 * 144;     // one K or V stage, bytes
    const uint32_t smu = smem_u32(smh);

    const int tid  = threadIdx.x;
    const int warp = tid >> 5;
    const int lane = tid & 31;
    const int g    = lane >> 2;
    const int t    = lane & 3;

    // side job: convert fc_w (fp32 -> fp16), grid-stride; ~3.5 float4/thread
    {
        int nthr = gridDim.x * 256;
        for (int i = blockIdx.x * 256 + tid; i < N4_WF; i += nthr) {
            float4 v = ((const float4*)wf)[i];
            __half2* o = (__half2*)g_wfc;
            o[2 * i]     = __floats2half2_rn(v.x, v.y);
            o[2 * i + 1] = __floats2half2_rn(v.z, v.w);
        }
    }

    const uint32_t offpat = (uint32_t)(((lane & 8) + (lane & 7)) * 144 + ((lane >> 4) << 4));
    const uint32_t qBase = smu + (uint32_t)(warp * 16 * 144) + offpat;
    const float LOG2E = 1.4426950408889634f;
    const uint32_t ONES2 = 0x3C003C00u;           // half2(1.0, 1.0)
    const uint32_t bb_ones[2] = {ONES2, ONES2};

    for (;;) {
        if (tid == 0) s_tile = atomicAdd(&g_ctr[2], 1);
        __syncthreads();
        const int tile = s_tile;
        if (tile >= NT) break;
        const int qt = tile & (SEQ / 128 - 1);          // 0..15
        const int h  = (tile >> 4) & (NHEAD - 1);       // 0..15
        const int b  = tile >> 8;                        // 0..1

        const size_t baseQK = ((size_t)(b * NHEAD + h)) * SEQ * HDIM;
        const __half* Qg = g_q + baseQK + (size_t)qt * 128 * HDIM;
        const __half* Kg = g_k + baseQK;
        const __half* Vg = g_v + ((size_t)(b * NHEAD + h)) * HDIM * SEQ;   // [d][s]

        #pragma unroll
        for (int i = 0; i < 4; i++) {
            int idx = tid + i * 256;
            int row = idx >> 3;
            int cp  = (idx & 7) << 3;
            CP_A16(smu + (uint32_t)(row * 144 + cp * 2), Qg + row * HDIM + cp);
        }
        CP_COMMIT();

        auto load_kv = [&](int st, int kt) {
            #pragma unroll
            for (int i = 0; i < 2; i++) {
                int idx = tid + i * 256;
                int row = idx >> 3;
                int cp  = (idx & 7) << 3;
                CP_A16(smu + (uint32_t)(QTB + st * STB + row * 144 + cp * 2),
                       Kg + ((size_t)kt * 64 + row) * HDIM + cp);
                CP_A16(smu + (uint32_t)(QTB + 2 * STB + st * STB + row * 144 + cp * 2),
                       Vg + (size_t)row * SEQ + kt * 64 + cp);
            }
            CP_COMMIT();
        };

        load_kv(0, 0);
        CP_WAIT1();       // Q group done (KV0 may still be in flight)
        __syncthreads();

        uint32_t qa[4][4];
        #pragma unroll
        for (int kk = 0; kk < 4; kk++)
            ldsm_x4(qa[kk][0], qa[kk][1], qa[kk][2], qa[kk][3], qBase + kk * 32);
        __syncthreads();

        float oc[8][4] = {};
        float lc[4]    = {};                    // tensor-core row sums (ones column)
        float m0 = -1e30f, m1 = -1e30f;

        int st = 0;
        for (int kt = 0; kt < SEQ / 64; kt++, st ^= 1) {
            if (kt + 1 < SEQ / 64) { load_kv(st ^ 1, kt + 1); CP_WAIT1(); }
            else                   { CP_WAIT0(); }
            __syncthreads();

            const uint32_t kBase = smu + (uint32_t)(QTB + st * STB) + offpat;
            const uint32_t vBase = smu + (uint32_t)(QTB + 2 * STB + st * STB) + offpat;

            // S = Q @ K^T  (already includes 1/sqrt(hd) via pre-scaled Q)
            float sc[8][4] = {};
            #pragma unroll
            for (int kk = 0; kk < 4; kk++) {
                uint32_t bb[8][2];
                #pragma unroll
                for (int nb = 0; nb < 4; nb++)
                    ldsm_x4(bb[2 * nb][0], bb[2 * nb + 1][0], bb[2 * nb][1], bb[2 * nb + 1][1],
                            kBase + nb * 16 * 144 + kk * 32);
                #pragma unroll
                for (int ni = 0; ni < 8; ni++)
                    mma_f16(sc[ni], qa[kk], bb[ni]);
            }

            // online softmax max update (rows g, g+8)
            float mx0 = -1e30f, mx1 = -1e30f;
            #pragma unroll
            for (int ni = 0; ni < 8; ni++) {
                mx0 = fmaxf(mx0, fmaxf(sc[ni][0], sc[ni][1]));
                mx1 = fmaxf(mx1, fmaxf(sc[ni][2], sc[ni][3]));
            }
            mx0 = fmaxf(mx0, __shfl_xor_sync(0xffffffffu, mx0, 1));
            mx0 = fmaxf(mx0, __shfl_xor_sync(0xffffffffu, mx0, 2));
            mx1 = fmaxf(mx1, __shfl_xor_sync(0xffffffffu, mx1, 1));
            mx1 = fmaxf(mx1, __shfl_xor_sync(0xffffffffu, mx1, 2));

            // warp-uniform rescale skip: if no lane's max grew, a0=a1=1 exactly.
            bool grew = (mx0 > m0) || (mx1 > m1);
            if (__any_sync(0xffffffffu, grew)) {
                float mn0 = fmaxf(m0, mx0);
                float mn1 = fmaxf(m1, mx1);
                float a0 = ex2f((m0 - mn0) * LOG2E);
                float a1 = ex2f((m1 - mn1) * LOG2E);
                m0 = mn0; m1 = mn1;
                lc[0] *= a0; lc[1] *= a0; lc[2] *= a1; lc[3] *= a1;
                #pragma unroll
                for (int ni = 0; ni < 8; ni++) {
                    oc[ni][0] *= a0; oc[ni][1] *= a0;
                    oc[ni][2] *= a1; oc[ni][3] *= a1;
                }
            }

            // P = exp2((s - m) * log2e) in half2 (one f16x2 MUFU per pair)
            const float mL0 = m0 * LOG2E;
            const float mL1 = m1 * LOG2E;
            uint32_t ph01[8], ph23[8];
            #pragma unroll
            for (int ni = 0; ni < 8; ni++) {
                ph01[ni] = h2ex2(pack_h2(fmaf(sc[ni][0], LOG2E, -mL0),
                                         fmaf(sc[ni][1], LOG2E, -mL0)));
                ph23[ni] = h2ex2(pack_h2(fmaf(sc[ni][2], LOG2E, -mL1),
                                         fmaf(sc[ni][3], LOG2E, -mL1)));
            }

            // O += P @ V ; l += P @ 1 (tensor-core row sum, same rescale path)
            #pragma unroll
            for (int kk = 0; kk < 4; kk++) {
                uint32_t pa[4];
                pa[0] = ph01[2 * kk];
                pa[1] = ph23[2 * kk];
                pa[2] = ph01[2 * kk + 1];
                pa[3] = ph23[2 * kk + 1];
                uint32_t bb[8][2];
                #pragma unroll
                for (int nb = 0; nb < 4; nb++)
                    ldsm_x4(bb[2 * nb][0], bb[2 * nb + 1][0], bb[2 * nb][1], bb[2 * nb + 1][1],
                            vBase + nb * 16 * 144 + kk * 32);
                #pragma unroll
                for (int ni = 0; ni < 8; ni++)
                    mma_f16(oc[ni], pa, bb[ni]);
                mma_f16(lc, pa, bb_ones);
            }
            __syncthreads();   // all warps done reading this KV stage
        }

        float i0 = 1.0f / lc[0];
        float i1 = 1.0f / lc[2];
        int r0 = qt * 128 + warp * 16 + g;
        __half* Og = g_att + (size_t)b * SEQ * EDIM + (size_t)h * HDIM;
        #pragma unroll
        for (int ni = 0; ni < 8; ni++) {
            int cc = ni * 8 + 2 * t;
            *(__half2*)(Og + (size_t)r0 * EDIM + cc) =
                __floats2half2_rn(oc[ni][0] * i0, oc[ni][1] * i0);
            *(__half2*)(Og + (size_t)(r0 + 8) * EDIM + cc) =
                __floats2half2_rn(oc[ni][2] * i1, oc[ni][3] * i1);
        }
        __syncthreads();   // protects smem AND s_tile before next grab
    }
}

extern "C" void kernel_launch(void* const* d_in, const int* in_sizes, int n_in,
                              void* d_out, int out_size)
{
    const float* x     = (const float*)d_in[0];
    const float* hmask = (const float*)d_in[1];
    const float* qkv_w = (const float*)d_in[2];
    const float* qkv_b = (const float*)d_in[3];
    const float* fc_w  = (const float*)d_in[4];
    const float* fc_b  = (const float*)d_in[5];
    float* out = (float*)d_out;

    const int gemm_smem = 3 * 2 * 128 * 144;                 // 110592 B
    const int fa_smem   = 128 * 144 + 4 * 64 * 144;          // 55296 B

    cudaFuncSetAttribute(gemm_f16_kernel<1>,
                         cudaFuncAttributeMaxDynamicSharedMemorySize, gemm_smem);
    cudaFuncSetAttribute(gemm_f16_kernel<0>,
                         cudaFuncAttributeMaxDynamicSharedMemorySize, gemm_smem);
    cudaFuncSetAttribute(flash_attn_kernel,
                         cudaFuncAttributeMaxDynamicSharedMemorySize, fa_smem);

    // 0) fp32->fp16 conversion of x + qkv_w, and scheduler-counter reset
    {
        int total4 = N4_X + N4_WQ;
        cvt_all_kernel<<<(total4 + 511) / 512, 512>>>(x, qkv_w);
    }

    const int PERSIST = 296;   // 148 SMs x 2 CTAs

    // 1) QKV projection + bias + head_mask (+1/8 into q) + scatter (stealing)
    {
        int NT  = (BATCH * SEQ / 128) * (3 * EDIM / 128);   // 768
        int NBX = 3 * EDIM / 128;                           // 24
        gemm_f16_kernel<1><<<PERSIST, 256, gemm_smem>>>(
            qkv_b, hmask, nullptr, BATCH * SEQ, 3 * EDIM, EDIM, NT, NBX);
    }

    // 2) flash attention -> g_att [B,S,D] (fp16, stealing) + fc_w convert
    {
        int NT = (SEQ / 128) * NHEAD * BATCH;               // 512
        flash_attn_kernel<<<PERSIST, 256, fa_smem>>>(NT, fc_w);
    }

    // 3) output projection + bias -> d_out (fp32, stealing)
    {
        int NT  = (BATCH * SEQ / 128) * (EDIM / 128);       // 256
        int NBX = EDIM / 128;                               // 8
        gemm_f16_kernel<0><<<PERSIST, 256, gemm_smem>>>(
            fc_b, nullptr, out, BATCH * SEQ, EDIM, EDIM, NT, NBX);
    }
}